// round 4
// baseline (speedup 1.0000x reference)
#include <cuda_runtime.h>
#include <cstdint>

// state: [2, 4096, 512] float32. The 4 CNOTs compose into one permutation of
// the 4096 row indices. SCATTER form: read rows linearly (sequential DRAM
// stream on cold fills), write to the permuted destination row.
//
// Forward map (where does source row i land): apply PAIRS in order.
//   (0,1):  dst ^= ((i>>11)&1) << 10
//   (2,3):  dst ^= ((i>>9)&1)  << 8
//   (5,2):  dst ^= ((i>>6)&1)  << 9
//   (11,7): dst ^= ((i>>0)&1)  << 4
// (big-endian: qubit q -> bit 11-q)

static __device__ __forceinline__ unsigned dst_index(unsigned i) {
    i ^= ((i >> 11) & 1u) << 10;  // (c=0,  t=1)
    i ^= ((i >> 9)  & 1u) << 8;   // (c=2,  t=3)
    i ^= ((i >> 6)  & 1u) << 9;   // (c=5,  t=2)
    i ^= ((i >> 0)  & 1u) << 4;   // (c=11, t=7)
    return i;
}

// 2*4096 rows * 128 float4/row = 2^20 float4. 2048 blocks * 256 threads,
// 2 float4 per thread (independent -> MLP=2), fully linear read stream.
__global__ __launch_bounds__(256) void cnot_scatter_copy(
    const float4* __restrict__ in, float4* __restrict__ out)
{
    unsigned base = (blockIdx.x * blockDim.x + threadIdx.x) * 2u;  // linear src float4 idx

    #pragma unroll
    for (int k = 0; k < 2; k++) {
        unsigned idx = base + (unsigned)k;          // consecutive -> coalesced seq read
        unsigned b4  = idx & 127u;
        unsigned row = idx >> 7;                    // 0 .. 8191
        unsigned i   = row & 4095u;
        unsigned n   = row >> 12;
        float4 v = __ldg(&in[idx]);
        unsigned d = (n << 12) | dst_index(i);
        out[(d << 7) | b4] = v;
    }
}

extern "C" void kernel_launch(void* const* d_in, const int* in_sizes, int n_in,
                              void* d_out, int out_size) {
    const float4* in  = (const float4*)d_in[0];
    float4*       out = (float4*)d_out;
    // 2^20 float4 / (256 threads * 2 per thread) = 2048 blocks
    cnot_scatter_copy<<<2048, 256>>>(in, out);
}

// round 5
// speedup vs baseline: 1.1691x; 1.1691x over previous
#include <cuda_runtime.h>
#include <cstdint>

// state: [2, 4096, 512] float32. The 4 CNOTs compose into one bit-twiddle
// permutation of the 4096 row indices. GATHER form (best so far):
// out[n, i, b] = in[n, src(i), b], rows = 512 contiguous floats.
//
// New in R5: write-through stores (st.global.wt) so output lines are CLEAN
// in L2 -> no dirty-eviction LTS crossing on the next graph replay.
// Steady-state LTS traffic drops from ~48 MB to ~32 MB per replay.

static __device__ __forceinline__ unsigned src_index(unsigned j) {
    // PAIRS [(0,1),(2,3),(5,2),(11,7)] applied in reverse for the source map
    // (big-endian: qubit q -> bit 11-q)
    j ^= ((j >> 0) & 1u) << 4;    // (c=11, t=7)
    j ^= ((j >> 6) & 1u) << 9;    // (c=5,  t=2)
    j ^= ((j >> 9) & 1u) << 8;    // (c=2,  t=3)
    j ^= ((j >> 11) & 1u) << 10;  // (c=0,  t=1)
    return j;
}

static __device__ __forceinline__ void stg_wt_v4(float4* p, float4 v) {
    asm volatile("st.global.wt.v4.f32 [%0], {%1, %2, %3, %4};"
                 :: "l"(p), "f"(v.x), "f"(v.y), "f"(v.z), "f"(v.w)
                 : "memory");
}

// 2*4096 rows * 128 float4/row = 2^20 float4. One float4 per thread,
// 4096 blocks x 256 threads (R1 config, best timed so far).
__global__ __launch_bounds__(256) void cnot_perm_copy_wt(
    const float4* __restrict__ in, float4* __restrict__ out)
{
    unsigned idx = blockIdx.x * blockDim.x + threadIdx.x;   // 0 .. 2^20-1
    unsigned b4  = idx & 127u;          // float4 column within row
    unsigned row = idx >> 7;            // 0 .. 8191
    unsigned i   = row & 4095u;         // basis index within block
    unsigned n   = row >> 12;           // block (0 or 1)

    unsigned src = src_index(i);
    float4 v = __ldg(&in[(((n << 12) | src) << 7) | b4]);
    stg_wt_v4(&out[idx], v);
}

extern "C" void kernel_launch(void* const* d_in, const int* in_sizes, int n_in,
                              void* d_out, int out_size) {
    const float4* in  = (const float4*)d_in[0];
    float4*       out = (float4*)d_out;
    cnot_perm_copy_wt<<<4096, 256>>>(in, out);
}

// round 6
// speedup vs baseline: 1.2037x; 1.0296x over previous
#include <cuda_runtime.h>
#include <cstdint>

// state: [2, 4096, 512] float32. The 4 CNOTs compose into one bit-twiddle
// permutation of the 4096 row indices. GATHER: out[n,i,:] = in[n,src(i),:].
// Rows are 512 floats = 2048 B contiguous.
//
// R6: 256-bit global accesses (Blackwell v8.f32) — one 32B load + one 32B
// store per thread. 64 v8-chunks per row; a warp covers 1 KB of one row per
// access round (fully contiguous burst on both sides).

static __device__ __forceinline__ unsigned src_index(unsigned j) {
    // PAIRS [(0,1),(2,3),(5,2),(11,7)] applied in reverse for the source map
    // (big-endian: qubit q -> bit 11-q)
    j ^= ((j >> 0) & 1u) << 4;    // (c=11, t=7)
    j ^= ((j >> 6) & 1u) << 9;    // (c=5,  t=2)
    j ^= ((j >> 9) & 1u) << 8;    // (c=2,  t=3)
    j ^= ((j >> 11) & 1u) << 10;  // (c=0,  t=1)
    return j;
}

// Total 2^20 float4 = 2^19 v8 (32B) chunks. 2048 blocks x 256 threads,
// one v8 per thread.
__global__ __launch_bounds__(256) void cnot_perm_copy_v8(
    const float* __restrict__ in, float* __restrict__ out)
{
    unsigned idx = blockIdx.x * blockDim.x + threadIdx.x;  // 0 .. 2^19-1
    unsigned c8  = idx & 63u;           // 32B chunk within row (64 per row)
    unsigned row = idx >> 6;            // 0 .. 8191
    unsigned i   = row & 4095u;
    unsigned n   = row >> 12;
    unsigned src = (n << 12) | src_index(i);

    const float* gsrc = in  + ((size_t)src * 512u + c8 * 8u);
    float*       gdst = out + ((size_t)row * 512u + c8 * 8u);

    float v0, v1, v2, v3, v4, v5, v6, v7;
    asm volatile(
        "ld.global.nc.v8.f32 {%0, %1, %2, %3, %4, %5, %6, %7}, [%8];"
        : "=f"(v0), "=f"(v1), "=f"(v2), "=f"(v3),
          "=f"(v4), "=f"(v5), "=f"(v6), "=f"(v7)
        : "l"(gsrc));
    asm volatile(
        "st.global.v8.f32 [%0], {%1, %2, %3, %4, %5, %6, %7, %8};"
        :: "l"(gdst),
           "f"(v0), "f"(v1), "f"(v2), "f"(v3),
           "f"(v4), "f"(v5), "f"(v6), "f"(v7)
        : "memory");
}

extern "C" void kernel_launch(void* const* d_in, const int* in_sizes, int n_in,
                              void* d_out, int out_size) {
    const float* in  = (const float*)d_in[0];
    float*       out = (float*)d_out;
    // 2^19 v8 chunks / 256 threads = 2048 blocks
    cnot_perm_copy_v8<<<2048, 256>>>(in, out);
}

// round 7
// speedup vs baseline: 1.2548x; 1.0425x over previous
#include <cuda_runtime.h>
#include <cstdint>

// state: [2, 4096, 512] float32. The 4 CNOTs compose into one bit-twiddle
// permutation of the 4096 row indices. GATHER: out[n,i,:] = in[n,src(i),:],
// rows = 512 floats = 2048 B contiguous.
//
// R7: combine the levers — 256-bit accesses (v8.f32, best cold time),
// 2 independent chunks per thread (MLP=2), single-wave grid (1024 blocks,
// ~7 CTAs/SM on 148 SMs, no wave transition).

static __device__ __forceinline__ unsigned src_index(unsigned j) {
    // PAIRS [(0,1),(2,3),(5,2),(11,7)] applied in reverse for the source map
    // (big-endian: qubit q -> bit 11-q)
    j ^= ((j >> 0) & 1u) << 4;    // (c=11, t=7)
    j ^= ((j >> 6) & 1u) << 9;    // (c=5,  t=2)
    j ^= ((j >> 9) & 1u) << 8;    // (c=2,  t=3)
    j ^= ((j >> 11) & 1u) << 10;  // (c=0,  t=1)
    return j;
}

// 2^19 v8 (32B) chunks total. 1024 blocks x 256 threads x 2 chunks/thread.
// Chunk k for a thread is at stride 2^18 so both loads are independent and
// each warp's accesses stay fully contiguous (1 KB per warp per round).
__global__ __launch_bounds__(256) void cnot_perm_copy_v8x2(
    const float* __restrict__ in, float* __restrict__ out)
{
    unsigned base = blockIdx.x * blockDim.x + threadIdx.x;  // 0 .. 2^18-1

    const float* gsrc[2];
    float*       gdst[2];
    #pragma unroll
    for (int k = 0; k < 2; k++) {
        unsigned idx = base + (unsigned)k * (1u << 18);     // 0 .. 2^19-1
        unsigned c8  = idx & 63u;        // 32B chunk within row
        unsigned row = idx >> 6;         // 0 .. 8191
        unsigned i   = row & 4095u;
        unsigned n   = row >> 12;
        unsigned src = (n << 12) | src_index(i);
        gsrc[k] = in  + ((size_t)src * 512u + c8 * 8u);
        gdst[k] = out + ((size_t)row * 512u + c8 * 8u);
    }

    float a0,a1,a2,a3,a4,a5,a6,a7;
    float b0,b1,b2,b3,b4,b5,b6,b7;
    asm volatile("ld.global.nc.v8.f32 {%0,%1,%2,%3,%4,%5,%6,%7}, [%8];"
        : "=f"(a0),"=f"(a1),"=f"(a2),"=f"(a3),
          "=f"(a4),"=f"(a5),"=f"(a6),"=f"(a7) : "l"(gsrc[0]));
    asm volatile("ld.global.nc.v8.f32 {%0,%1,%2,%3,%4,%5,%6,%7}, [%8];"
        : "=f"(b0),"=f"(b1),"=f"(b2),"=f"(b3),
          "=f"(b4),"=f"(b5),"=f"(b6),"=f"(b7) : "l"(gsrc[1]));
    asm volatile("st.global.v8.f32 [%0], {%1,%2,%3,%4,%5,%6,%7,%8};"
        :: "l"(gdst[0]),
           "f"(a0),"f"(a1),"f"(a2),"f"(a3),
           "f"(a4),"f"(a5),"f"(a6),"f"(a7) : "memory");
    asm volatile("st.global.v8.f32 [%0], {%1,%2,%3,%4,%5,%6,%7,%8};"
        :: "l"(gdst[1]),
           "f"(b0),"f"(b1),"f"(b2),"f"(b3),
           "f"(b4),"f"(b5),"f"(b6),"f"(b7) : "memory");
}

extern "C" void kernel_launch(void* const* d_in, const int* in_sizes, int n_in,
                              void* d_out, int out_size) {
    const float* in  = (const float*)d_in[0];
    float*       out = (float*)d_out;
    // 2^19 chunks / (256 threads * 2) = 1024 blocks (single wave)
    cnot_perm_copy_v8x2<<<1024, 256>>>(in, out);
}